// round 1
// baseline (speedup 1.0000x reference)
#include <cuda_runtime.h>
#include <cuda_bf16.h>

// Problem constants (from reference)
#define BATCH 16384
#define EMBED 1024
#define SEQ   7
#define E4    (EMBED / 4)       // 256 float4 lanes per row
#define ROWS_PER_BLOCK 4
#define THREADS E4              // 256

__device__ __forceinline__ float sigf(float x) {
    return 1.0f / (1.0f + __expf(-x));
}

// Scalar cascade for one channel given 7 gathered values and 10 weights.
__device__ __forceinline__ float cascade(
    const float h0, const float h1, const float h2, const float h3,
    const float h4, const float h5, const float h6,
    const float w10, const float w11,
    const float w20, const float w21,
    const float w30, const float w31, const float w32,
    const float w40, const float w41, const float w42)
{
    float h[7] = {h0, h1, h2, h3, h4, h5, h6};
    float a[6];
#pragma unroll
    for (int t = 0; t < 6; ++t)
        a[t] = sigf(fmaf(w11, h[t + 1], w10 * h[t]));
    float p[5];
#pragma unroll
    for (int t = 0; t < 5; ++t)
        p[t] = sigf(fmaf(w21, a[t + 1], w20 * a[t]));
    float q[3];
#pragma unroll
    for (int t = 0; t < 3; ++t)
        q[t] = sigf(fmaf(w32, p[t + 2], fmaf(w31, p[t + 1], w30 * p[t])));
    return sigf(fmaf(w42, q[2], fmaf(w41, q[1], w40 * q[0])));
}

__global__ void __launch_bounds__(THREADS)
conv_cascade_kernel(const int* __restrict__ X,
                    const float4* __restrict__ emb,     // (VOCAB, E4)
                    const float4* __restrict__ c1,      // (2, E4)
                    const float4* __restrict__ c2,      // (2, E4)
                    const float4* __restrict__ c3,      // (3, E4)
                    const float4* __restrict__ c4,      // (3, E4)
                    float4* __restrict__ out)           // (BATCH, E4)
{
    const int e4 = threadIdx.x;                 // 0..255  (channel group)
    const int b0 = blockIdx.x * ROWS_PER_BLOCK; // first batch row of this block

    // Stage indices for the block's rows through shared memory.
    __shared__ int idx[ROWS_PER_BLOCK][SEQ];
    if (threadIdx.x < ROWS_PER_BLOCK * SEQ) {
        int r = threadIdx.x / SEQ;
        int t = threadIdx.x % SEQ;
        idx[r][t] = X[(b0 + r) * SEQ + t];
    }

    // Per-thread conv weights (10 float4s), reused across ROWS_PER_BLOCK rows.
    const float4 w10 = c1[0 * E4 + e4];
    const float4 w11 = c1[1 * E4 + e4];
    const float4 w20 = c2[0 * E4 + e4];
    const float4 w21 = c2[1 * E4 + e4];
    const float4 w30 = c3[0 * E4 + e4];
    const float4 w31 = c3[1 * E4 + e4];
    const float4 w32 = c3[2 * E4 + e4];
    const float4 w40 = c4[0 * E4 + e4];
    const float4 w41 = c4[1 * E4 + e4];
    const float4 w42 = c4[2 * E4 + e4];

    __syncthreads();

#pragma unroll
    for (int r = 0; r < ROWS_PER_BLOCK; ++r) {
        // Gather the 7 embedding float4s for this (row, channel-group).
        float4 h[SEQ];
#pragma unroll
        for (int t = 0; t < SEQ; ++t) {
            long row = (long)idx[r][t];
            h[t] = __ldg(&emb[row * E4 + e4]);
        }

        float4 res;
        res.x = cascade(h[0].x, h[1].x, h[2].x, h[3].x, h[4].x, h[5].x, h[6].x,
                        w10.x, w11.x, w20.x, w21.x, w30.x, w31.x, w32.x,
                        w40.x, w41.x, w42.x);
        res.y = cascade(h[0].y, h[1].y, h[2].y, h[3].y, h[4].y, h[5].y, h[6].y,
                        w10.y, w11.y, w20.y, w21.y, w30.y, w31.y, w32.y,
                        w40.y, w41.y, w42.y);
        res.z = cascade(h[0].z, h[1].z, h[2].z, h[3].z, h[4].z, h[5].z, h[6].z,
                        w10.z, w11.z, w20.z, w21.z, w30.z, w31.z, w32.z,
                        w40.z, w41.z, w42.z);
        res.w = cascade(h[0].w, h[1].w, h[2].w, h[3].w, h[4].w, h[5].w, h[6].w,
                        w10.w, w11.w, w20.w, w21.w, w30.w, w31.w, w32.w,
                        w40.w, w41.w, w42.w);

        out[(long)(b0 + r) * E4 + e4] = res;
    }
}

extern "C" void kernel_launch(void* const* d_in, const int* in_sizes, int n_in,
                              void* d_out, int out_size)
{
    const int*    X    = (const int*)d_in[0];
    const float4* emb  = (const float4*)d_in[1];
    const float4* c1   = (const float4*)d_in[2];
    const float4* c2   = (const float4*)d_in[3];
    const float4* c3   = (const float4*)d_in[4];
    const float4* c4   = (const float4*)d_in[5];
    float4*       out  = (float4*)d_out;

    dim3 grid(BATCH / ROWS_PER_BLOCK);
    dim3 block(THREADS);
    conv_cascade_kernel<<<grid, block>>>(X, emb, c1, c2, c3, c4, out);
}

// round 2
// speedup vs baseline: 2.2145x; 2.2145x over previous
#include <cuda_runtime.h>
#include <cuda_bf16.h>

// Problem constants (from reference)
#define BATCH 16384
#define EMBED 1024
#define SEQ   7
#define E4    (EMBED / 4)       // 256 float4 lanes per row
#define ROWS_PER_BLOCK 4
#define THREADS E4              // 256

// sigmoid via HW tanh: sigma(x) = 0.5*tanh(0.5x) + 0.5   (3 instrs, 1 MUFU)
__device__ __forceinline__ float sigf(float x) {
    float t;
    asm("tanh.approx.f32 %0, %1;" : "=f"(t) : "f"(x * 0.5f));
    return fmaf(t, 0.5f, 0.5f);
}

// Scalar cascade for one channel given 7 gathered values and 10 weights.
__device__ __forceinline__ float cascade(
    const float h0, const float h1, const float h2, const float h3,
    const float h4, const float h5, const float h6,
    const float w10, const float w11,
    const float w20, const float w21,
    const float w30, const float w31, const float w32,
    const float w40, const float w41, const float w42)
{
    float h[7] = {h0, h1, h2, h3, h4, h5, h6};
    float a[6];
#pragma unroll
    for (int t = 0; t < 6; ++t)
        a[t] = sigf(fmaf(w11, h[t + 1], w10 * h[t]));
    float p[5];
#pragma unroll
    for (int t = 0; t < 5; ++t)
        p[t] = sigf(fmaf(w21, a[t + 1], w20 * a[t]));
    float q[3];
#pragma unroll
    for (int t = 0; t < 3; ++t)
        q[t] = sigf(fmaf(w32, p[t + 2], fmaf(w31, p[t + 1], w30 * p[t])));
    return sigf(fmaf(w42, q[2], fmaf(w41, q[1], w40 * q[0])));
}

__global__ void __launch_bounds__(THREADS, 4)
conv_cascade_kernel(const int* __restrict__ X,
                    const float4* __restrict__ emb,     // (VOCAB, E4)
                    const float4* __restrict__ c1,      // (2, E4)
                    const float4* __restrict__ c2,      // (2, E4)
                    const float4* __restrict__ c3,      // (3, E4)
                    const float4* __restrict__ c4,      // (3, E4)
                    float4* __restrict__ out)           // (BATCH, E4)
{
    const int e4 = threadIdx.x;                 // 0..255  (channel group)
    const int b0 = blockIdx.x * ROWS_PER_BLOCK; // first batch row of this block

    // Stage indices for the block's rows through shared memory.
    __shared__ int idx[ROWS_PER_BLOCK][SEQ];
    if (threadIdx.x < ROWS_PER_BLOCK * SEQ) {
        int r = threadIdx.x / SEQ;
        int t = threadIdx.x % SEQ;
        idx[r][t] = X[(b0 + r) * SEQ + t];
    }

    // Per-thread conv weights (10 float4s), reused across ROWS_PER_BLOCK rows.
    const float4 w10 = c1[0 * E4 + e4];
    const float4 w11 = c1[1 * E4 + e4];
    const float4 w20 = c2[0 * E4 + e4];
    const float4 w21 = c2[1 * E4 + e4];
    const float4 w30 = c3[0 * E4 + e4];
    const float4 w31 = c3[1 * E4 + e4];
    const float4 w32 = c3[2 * E4 + e4];
    const float4 w40 = c4[0 * E4 + e4];
    const float4 w41 = c4[1 * E4 + e4];
    const float4 w42 = c4[2 * E4 + e4];

    __syncthreads();

#pragma unroll
    for (int r = 0; r < ROWS_PER_BLOCK; ++r) {
        // Gather the 7 embedding float4s for this (row, channel-group).
        float4 h[SEQ];
#pragma unroll
        for (int t = 0; t < SEQ; ++t) {
            long row = (long)idx[r][t];
            h[t] = __ldg(&emb[row * E4 + e4]);
        }

        float4 res;
        res.x = cascade(h[0].x, h[1].x, h[2].x, h[3].x, h[4].x, h[5].x, h[6].x,
                        w10.x, w11.x, w20.x, w21.x, w30.x, w31.x, w32.x,
                        w40.x, w41.x, w42.x);
        res.y = cascade(h[0].y, h[1].y, h[2].y, h[3].y, h[4].y, h[5].y, h[6].y,
                        w10.y, w11.y, w20.y, w21.y, w30.y, w31.y, w32.y,
                        w40.y, w41.y, w42.y);
        res.z = cascade(h[0].z, h[1].z, h[2].z, h[3].z, h[4].z, h[5].z, h[6].z,
                        w10.z, w11.z, w20.z, w21.z, w30.z, w31.z, w32.z,
                        w40.z, w41.z, w42.z);
        res.w = cascade(h[0].w, h[1].w, h[2].w, h[3].w, h[4].w, h[5].w, h[6].w,
                        w10.w, w11.w, w20.w, w21.w, w30.w, w31.w, w32.w,
                        w40.w, w41.w, w42.w);

        out[(long)(b0 + r) * E4 + e4] = res;
    }
}

extern "C" void kernel_launch(void* const* d_in, const int* in_sizes, int n_in,
                              void* d_out, int out_size)
{
    const int*    X    = (const int*)d_in[0];
    const float4* emb  = (const float4*)d_in[1];
    const float4* c1   = (const float4*)d_in[2];
    const float4* c2   = (const float4*)d_in[3];
    const float4* c3   = (const float4*)d_in[4];
    const float4* c4   = (const float4*)d_in[5];
    float4*       out  = (float4*)d_out;

    dim3 grid(BATCH / ROWS_PER_BLOCK);
    dim3 block(THREADS);
    conv_cascade_kernel<<<grid, block>>>(X, emb, c1, c2, c3, c4, out);
}

// round 4
// speedup vs baseline: 2.2168x; 1.0010x over previous
#include <cuda_runtime.h>
#include <cuda_bf16.h>
#include <cstdint>

// Problem constants (from reference)
#define BATCH 16384
#define EMBED 1024
#define SEQ   7
#define E4    (EMBED / 4)       // 256 float4 lanes per row
#define ROWS_PER_BLOCK 4
#define THREADS E4              // 256

// sigmoid via HW tanh: sigma(x) = 0.5*tanh(0.5x) + 0.5   (3 instrs, 1 MUFU)
__device__ __forceinline__ float sigf(float x) {
    float t;
    asm("tanh.approx.f32 %0, %1;" : "=f"(t) : "f"(x * 0.5f));
    return fmaf(t, 0.5f, 0.5f);
}

// L2 evict_last access policy (fraction 1.0) — keeps the emb table resident.
__device__ __forceinline__ uint64_t make_persist_policy() {
    uint64_t pol;
    asm("createpolicy.fractional.L2::evict_last.b64 %0, 1.0;" : "=l"(pol));
    return pol;
}

// emb gather: non-coherent load with the persist policy attached.
__device__ __forceinline__ float4 ldg_persist(const float4* p, uint64_t pol) {
    float4 v;
    asm("ld.global.nc.L2::cache_hint.v4.f32 {%0,%1,%2,%3}, [%4], %5;"
        : "=f"(v.x), "=f"(v.y), "=f"(v.z), "=f"(v.w)
        : "l"(p), "l"(pol));
    return v;
}

// Scalar cascade for one channel given 7 gathered values and 10 weights.
__device__ __forceinline__ float cascade(
    const float h0, const float h1, const float h2, const float h3,
    const float h4, const float h5, const float h6,
    const float w10, const float w11,
    const float w20, const float w21,
    const float w30, const float w31, const float w32,
    const float w40, const float w41, const float w42)
{
    float h[7] = {h0, h1, h2, h3, h4, h5, h6};
    float a[6];
#pragma unroll
    for (int t = 0; t < 6; ++t)
        a[t] = sigf(fmaf(w11, h[t + 1], w10 * h[t]));
    float p[5];
#pragma unroll
    for (int t = 0; t < 5; ++t)
        p[t] = sigf(fmaf(w21, a[t + 1], w20 * a[t]));
    float q[3];
#pragma unroll
    for (int t = 0; t < 3; ++t)
        q[t] = sigf(fmaf(w32, p[t + 2], fmaf(w31, p[t + 1], w30 * p[t])));
    return sigf(fmaf(w42, q[2], fmaf(w41, q[1], w40 * q[0])));
}

__global__ void __launch_bounds__(THREADS, 4)
conv_cascade_kernel(const int* __restrict__ X,
                    const float4* __restrict__ emb,     // (VOCAB, E4)
                    const float4* __restrict__ c1,      // (2, E4)
                    const float4* __restrict__ c2,      // (2, E4)
                    const float4* __restrict__ c3,      // (3, E4)
                    const float4* __restrict__ c4,      // (3, E4)
                    float4* __restrict__ out)           // (BATCH, E4)
{
    const int e4 = threadIdx.x;                 // 0..255  (channel group)
    const int b0 = blockIdx.x * ROWS_PER_BLOCK; // first batch row of this block

    const uint64_t pol = make_persist_policy();

    // Stage indices for the block's rows through shared memory.
    __shared__ int idx[ROWS_PER_BLOCK][SEQ];
    if (threadIdx.x < ROWS_PER_BLOCK * SEQ) {
        int r = threadIdx.x / SEQ;
        int t = threadIdx.x % SEQ;
        idx[r][t] = X[(b0 + r) * SEQ + t];
    }

    // Per-thread conv weights (10 float4s), reused across ROWS_PER_BLOCK rows.
    const float4 w10 = c1[0 * E4 + e4];
    const float4 w11 = c1[1 * E4 + e4];
    const float4 w20 = c2[0 * E4 + e4];
    const float4 w21 = c2[1 * E4 + e4];
    const float4 w30 = c3[0 * E4 + e4];
    const float4 w31 = c3[1 * E4 + e4];
    const float4 w32 = c3[2 * E4 + e4];
    const float4 w40 = c4[0 * E4 + e4];
    const float4 w41 = c4[1 * E4 + e4];
    const float4 w42 = c4[2 * E4 + e4];

    __syncthreads();

#pragma unroll
    for (int r = 0; r < ROWS_PER_BLOCK; ++r) {
        // Gather the 7 embedding float4s for this (row, channel-group).
        float4 h[SEQ];
#pragma unroll
        for (int t = 0; t < SEQ; ++t) {
            long row = (long)idx[r][t];
            h[t] = ldg_persist(&emb[row * E4 + e4], pol);
        }

        float4 res;
        res.x = cascade(h[0].x, h[1].x, h[2].x, h[3].x, h[4].x, h[5].x, h[6].x,
                        w10.x, w11.x, w20.x, w21.x, w30.x, w31.x, w32.x,
                        w40.x, w41.x, w42.x);
        res.y = cascade(h[0].y, h[1].y, h[2].y, h[3].y, h[4].y, h[5].y, h[6].y,
                        w10.y, w11.y, w20.y, w21.y, w30.y, w31.y, w32.y,
                        w40.y, w41.y, w42.y);
        res.z = cascade(h[0].z, h[1].z, h[2].z, h[3].z, h[4].z, h[5].z, h[6].z,
                        w10.z, w11.z, w20.z, w21.z, w30.z, w31.z, w32.z,
                        w40.z, w41.z, w42.z);
        res.w = cascade(h[0].w, h[1].w, h[2].w, h[3].w, h[4].w, h[5].w, h[6].w,
                        w10.w, w11.w, w20.w, w21.w, w30.w, w31.w, w32.w,
                        w40.w, w41.w, w42.w);

        // Streaming store: don't let the output displace emb in L2.
        __stcs(&out[(long)(b0 + r) * E4 + e4], res);
    }
}

extern "C" void kernel_launch(void* const* d_in, const int* in_sizes, int n_in,
                              void* d_out, int out_size)
{
    const int*    X    = (const int*)d_in[0];
    const float4* emb  = (const float4*)d_in[1];
    const float4* c1   = (const float4*)d_in[2];
    const float4* c2   = (const float4*)d_in[3];
    const float4* c3   = (const float4*)d_in[4];
    const float4* c4   = (const float4*)d_in[5];
    float4*       out  = (float4*)d_out;

    dim3 grid(BATCH / ROWS_PER_BLOCK);
    dim3 block(THREADS);
    conv_cascade_kernel<<<grid, block>>>(X, emb, c1, c2, c3, c4, out);
}

// round 5
// speedup vs baseline: 2.2214x; 1.0021x over previous
#include <cuda_runtime.h>
#include <cuda_bf16.h>
#include <cstdint>

// Problem constants (from reference)
#define BATCH 16384
#define EMBED 1024
#define SEQ   7
#define E4    (EMBED / 4)       // 256 float4 lanes per full row
#define EQ4   64                // float4 lanes per quarter (256 channels)
#define NQ    4                 // number of channel quarters (launches)
#define ROWS_PER_CTA 8          // batch rows per block
#define ROWS_PER_IT  4          // rows processed per iteration (256 thr / 64 lanes)
#define THREADS 256

// sigmoid via HW tanh: sigma(x) = 0.5*tanh(0.5x) + 0.5   (3 instrs, 1 MUFU)
__device__ __forceinline__ float sigf(float x) {
    float t;
    asm("tanh.approx.f32 %0, %1;" : "=f"(t) : "f"(x * 0.5f));
    return fmaf(t, 0.5f, 0.5f);
}

// Scalar cascade for one channel given 7 gathered values and 10 weights.
__device__ __forceinline__ float cascade(
    const float h0, const float h1, const float h2, const float h3,
    const float h4, const float h5, const float h6,
    const float w10, const float w11,
    const float w20, const float w21,
    const float w30, const float w31, const float w32,
    const float w40, const float w41, const float w42)
{
    float h[7] = {h0, h1, h2, h3, h4, h5, h6};
    float a[6];
#pragma unroll
    for (int t = 0; t < 6; ++t)
        a[t] = sigf(fmaf(w11, h[t + 1], w10 * h[t]));
    float p[5];
#pragma unroll
    for (int t = 0; t < 5; ++t)
        p[t] = sigf(fmaf(w21, a[t + 1], w20 * a[t]));
    float q[3];
#pragma unroll
    for (int t = 0; t < 3; ++t)
        q[t] = sigf(fmaf(w32, p[t + 2], fmaf(w31, p[t + 1], w30 * p[t])));
    return sigf(fmaf(w42, q[2], fmaf(w41, q[1], w40 * q[0])));
}

// One launch processes channel quarter [e4_base, e4_base+EQ4) float4-lanes
// for the whole batch. Table footprint per launch: 32000 * 1KB = 32.7MB << L2.
__global__ void __launch_bounds__(THREADS, 4)
conv_cascade_q_kernel(const int* __restrict__ X,
                      const float4* __restrict__ emb,   // (VOCAB, E4)
                      const float4* __restrict__ c1,    // (2, E4)
                      const float4* __restrict__ c2,    // (2, E4)
                      const float4* __restrict__ c3,    // (3, E4)
                      const float4* __restrict__ c4,    // (3, E4)
                      float4* __restrict__ out,         // (BATCH, E4)
                      int e4_base)
{
    const int lane = threadIdx.x & (EQ4 - 1);           // 0..63 float4 lane in quarter
    const int rsub = threadIdx.x >> 6;                  // 0..3 row within iteration
    const int e4   = e4_base + lane;                    // full-row float4 index
    const int b0   = blockIdx.x * ROWS_PER_CTA;         // first batch row

    // Stage the CTA's indices through shared memory (one sync total).
    __shared__ int idx[ROWS_PER_CTA][SEQ];
    if (threadIdx.x < ROWS_PER_CTA * SEQ) {
        int r = threadIdx.x / SEQ;
        int t = threadIdx.x % SEQ;
        idx[r][t] = X[(b0 + r) * SEQ + t];
    }

    // Per-thread conv weights (10 float4s), held across all rows.
    const float4 w10 = c1[0 * E4 + e4];
    const float4 w11 = c1[1 * E4 + e4];
    const float4 w20 = c2[0 * E4 + e4];
    const float4 w21 = c2[1 * E4 + e4];
    const float4 w30 = c3[0 * E4 + e4];
    const float4 w31 = c3[1 * E4 + e4];
    const float4 w32 = c3[2 * E4 + e4];
    const float4 w40 = c4[0 * E4 + e4];
    const float4 w41 = c4[1 * E4 + e4];
    const float4 w42 = c4[2 * E4 + e4];

    __syncthreads();

#pragma unroll
    for (int it = 0; it < ROWS_PER_CTA / ROWS_PER_IT; ++it) {
        const int r = it * ROWS_PER_IT + rsub;

        // Gather the 7 embedding float4s for this (row, channel-group).
        float4 h[SEQ];
#pragma unroll
        for (int t = 0; t < SEQ; ++t) {
            long row = (long)idx[r][t];
            h[t] = __ldg(&emb[row * E4 + e4]);
        }

        float4 res;
        res.x = cascade(h[0].x, h[1].x, h[2].x, h[3].x, h[4].x, h[5].x, h[6].x,
                        w10.x, w11.x, w20.x, w21.x, w30.x, w31.x, w32.x,
                        w40.x, w41.x, w42.x);
        res.y = cascade(h[0].y, h[1].y, h[2].y, h[3].y, h[4].y, h[5].y, h[6].y,
                        w10.y, w11.y, w20.y, w21.y, w30.y, w31.y, w32.y,
                        w40.y, w41.y, w42.y);
        res.z = cascade(h[0].z, h[1].z, h[2].z, h[3].z, h[4].z, h[5].z, h[6].z,
                        w10.z, w11.z, w20.z, w21.z, w30.z, w31.z, w32.z,
                        w40.z, w41.z, w42.z);
        res.w = cascade(h[0].w, h[1].w, h[2].w, h[3].w, h[4].w, h[5].w, h[6].w,
                        w10.w, w11.w, w20.w, w21.w, w30.w, w31.w, w32.w,
                        w40.w, w41.w, w42.w);

        // Streaming store: keep the write stream from displacing emb in L2.
        __stcs(&out[(long)(b0 + r) * E4 + e4], res);
    }
}

extern "C" void kernel_launch(void* const* d_in, const int* in_sizes, int n_in,
                              void* d_out, int out_size)
{
    const int*    X    = (const int*)d_in[0];
    const float4* emb  = (const float4*)d_in[1];
    const float4* c1   = (const float4*)d_in[2];
    const float4* c2   = (const float4*)d_in[3];
    const float4* c3   = (const float4*)d_in[4];
    const float4* c4   = (const float4*)d_in[5];
    float4*       out  = (float4*)d_out;

    dim3 grid(BATCH / ROWS_PER_CTA);   // 2048 CTAs per launch
    dim3 block(THREADS);
    // 4 sequential launches, one channel quarter each: every launch's gather
    // footprint (32.7MB) fits comfortably in L2.
    for (int q = 0; q < NQ; ++q) {
        conv_cascade_q_kernel<<<grid, block>>>(X, emb, c1, c2, c3, c4, out,
                                               q * EQ4);
    }
}

// round 6
// speedup vs baseline: 2.5496x; 1.1477x over previous
#include <cuda_runtime.h>
#include <cuda_bf16.h>
#include <cstdint>

// Problem constants (from reference)
#define BATCH 16384
#define EMBED 1024
#define SEQ   7
#define E4    (EMBED / 4)       // 256 float4 lanes per full row
#define EQ4   64                // float4 lanes per quarter (256 channels)
#define NQ    4                 // number of channel quarters (launches)
#define ROWS_PER_CTA 16
#define ROWS_PER_IT  4          // 256 threads / 64 lanes
#define THREADS 256

typedef unsigned long long u64;

// ---- f32x2 packed helpers (Blackwell) ----
__device__ __forceinline__ u64 pack2(float lo, float hi) {
    u64 r; asm("mov.b64 %0, {%1,%2};" : "=l"(r) : "f"(lo), "f"(hi)); return r;
}
__device__ __forceinline__ void unpack2(u64 v, float& lo, float& hi) {
    asm("mov.b64 {%0,%1}, %2;" : "=f"(lo), "=f"(hi) : "l"(v));
}
__device__ __forceinline__ u64 fma2(u64 a, u64 b, u64 c) {
    u64 d; asm("fma.rn.f32x2 %0, %1, %2, %3;" : "=l"(d) : "l"(a), "l"(b), "l"(c));
    return d;
}
__device__ __forceinline__ u64 mul2(u64 a, u64 b) {
    u64 d; asm("mul.rn.f32x2 %0, %1, %2;" : "=l"(d) : "l"(a), "l"(b));
    return d;
}
// packed tanh via two scalar MUFU ops
__device__ __forceinline__ u64 tanh2(u64 z) {
    float lo, hi;
    unpack2(z, lo, hi);
    asm("tanh.approx.f32 %0, %0;" : "+f"(lo));
    asm("tanh.approx.f32 %0, %0;" : "+f"(hi));
    return pack2(lo, hi);
}

// scaled float4 -> two packed f32x2
__device__ __forceinline__ ulonglong2 pack4s(float4 v, float s) {
    ulonglong2 r;
    r.x = pack2(v.x * s, v.y * s);
    r.y = pack2(v.z * s, v.w * s);
    return r;
}

// One launch processes channel quarter [e4_base, e4_base+EQ4) float4-lanes
// for the whole batch (gather footprint 32.7MB -> L2-resident).
__global__ void __launch_bounds__(THREADS, 4)
conv_cascade_q_kernel(const int* __restrict__ X,
                      const float4* __restrict__ emb,   // (VOCAB, E4)
                      const float4* __restrict__ c1,    // (2, E4)
                      const float4* __restrict__ c2,    // (2, E4)
                      const float4* __restrict__ c3,    // (3, E4)
                      const float4* __restrict__ c4,    // (3, E4)
                      float4* __restrict__ out,         // (BATCH, E4)
                      int e4_base)
{
    const int lane = threadIdx.x & (EQ4 - 1);           // 0..63
    const int rsub = threadIdx.x >> 6;                  // 0..3
    const int e4   = e4_base + lane;
    const int b0   = blockIdx.x * ROWS_PER_CTA;

    // Tanh-domain scaled weights, one set per lane, computed once.
    // Layout: [0]=w10/2 [1]=w11/2 | [2]=w20/4 [3]=w21/4 [4]=b2
    //         [5..7]=w3x/4 [8]=b3 | [9..11]=w4x/4 [12]=b4
    __shared__ ulonglong2 Wsm[13][EQ4];
    __shared__ int idx[ROWS_PER_CTA][SEQ];

    if (threadIdx.x < ROWS_PER_CTA * SEQ) {
        int r = threadIdx.x / SEQ;
        int t = threadIdx.x % SEQ;
        idx[r][t] = X[(b0 + r) * SEQ + t];
    }

    if (threadIdx.x < EQ4) {
        const int l = threadIdx.x;
        const int g = e4_base + l;
        float4 a0 = c1[0 * E4 + g], a1 = c1[1 * E4 + g];
        float4 d0 = c2[0 * E4 + g], d1 = c2[1 * E4 + g];
        float4 e0 = c3[0 * E4 + g], e1 = c3[1 * E4 + g], e2 = c3[2 * E4 + g];
        float4 f0 = c4[0 * E4 + g], f1 = c4[1 * E4 + g], f2 = c4[2 * E4 + g];

        Wsm[0][l] = pack4s(a0, 0.5f);
        Wsm[1][l] = pack4s(a1, 0.5f);
        Wsm[2][l] = pack4s(d0, 0.25f);
        Wsm[3][l] = pack4s(d1, 0.25f);
        float4 b2 = make_float4(d0.x + d1.x, d0.y + d1.y, d0.z + d1.z, d0.w + d1.w);
        Wsm[4][l] = pack4s(b2, 0.25f);
        Wsm[5][l] = pack4s(e0, 0.25f);
        Wsm[6][l] = pack4s(e1, 0.25f);
        Wsm[7][l] = pack4s(e2, 0.25f);
        float4 b3 = make_float4(e0.x + e1.x + e2.x, e0.y + e1.y + e2.y,
                                e0.z + e1.z + e2.z, e0.w + e1.w + e2.w);
        Wsm[8][l] = pack4s(b3, 0.25f);
        Wsm[9][l]  = pack4s(f0, 0.25f);
        Wsm[10][l] = pack4s(f1, 0.25f);
        Wsm[11][l] = pack4s(f2, 0.25f);
        float4 b4 = make_float4(f0.x + f1.x + f2.x, f0.y + f1.y + f2.y,
                                f0.z + f1.z + f2.z, f0.w + f1.w + f2.w);
        Wsm[12][l] = pack4s(b4, 0.25f);
    }

    __syncthreads();

    const u64 HALF2 = pack2(0.5f, 0.5f);

#pragma unroll 1
    for (int it = 0; it < ROWS_PER_CTA / ROWS_PER_IT; ++it) {
        const int r = it * ROWS_PER_IT + rsub;

        // Gather 7 embedding float4s -> packed pairs.
        u64 ha[SEQ], hb[SEQ];
#pragma unroll
        for (int t = 0; t < SEQ; ++t) {
            long row = (long)idx[r][t];
            float4 h = __ldg(&emb[row * E4 + e4]);
            ha[t] = pack2(h.x, h.y);
            hb[t] = pack2(h.z, h.w);
        }

        // Stage 1 (size-2, raw input, scale 1/2, no bias)
        ulonglong2 W0 = Wsm[0][lane], W1 = Wsm[1][lane];
        u64 pa[6], pb[6];
#pragma unroll
        for (int t = 0; t < 6; ++t) {
            pa[t] = tanh2(fma2(W0.x, ha[t], mul2(W1.x, ha[t + 1])));
            pb[t] = tanh2(fma2(W0.y, hb[t], mul2(W1.y, hb[t + 1])));
        }

        // Stage 2 (size-2, tanh-domain, scale 1/4 + bias)
        ulonglong2 V0 = Wsm[2][lane], V1 = Wsm[3][lane], B2 = Wsm[4][lane];
        u64 qa[5], qb[5];
#pragma unroll
        for (int t = 0; t < 5; ++t) {
            qa[t] = tanh2(fma2(V0.x, pa[t], fma2(V1.x, pa[t + 1], B2.x)));
            qb[t] = tanh2(fma2(V0.y, pb[t], fma2(V1.y, pb[t + 1], B2.y)));
        }

        // Stage 3 (size-3)
        ulonglong2 U0 = Wsm[5][lane], U1 = Wsm[6][lane], U2 = Wsm[7][lane],
                   B3 = Wsm[8][lane];
        u64 sa[3], sb[3];
#pragma unroll
        for (int t = 0; t < 3; ++t) {
            sa[t] = tanh2(fma2(U0.x, qa[t],
                        fma2(U1.x, qa[t + 1], fma2(U2.x, qa[t + 2], B3.x))));
            sb[t] = tanh2(fma2(U0.y, qb[t],
                        fma2(U1.y, qb[t + 1], fma2(U2.y, qb[t + 2], B3.y))));
        }

        // Stage 4 (size-3) + final affine back to sigma
        ulonglong2 T0 = Wsm[9][lane], T1 = Wsm[10][lane], T2 = Wsm[11][lane],
                   B4 = Wsm[12][lane];
        u64 ra = tanh2(fma2(T0.x, sa[0],
                       fma2(T1.x, sa[1], fma2(T2.x, sa[2], B4.x))));
        u64 rb = tanh2(fma2(T0.y, sb[0],
                       fma2(T1.y, sb[1], fma2(T2.y, sb[2], B4.y))));
        ra = fma2(ra, HALF2, HALF2);
        rb = fma2(rb, HALF2, HALF2);

        float4 res;
        unpack2(ra, res.x, res.y);
        unpack2(rb, res.z, res.w);
        __stcs(&out[(long)(b0 + r) * E4 + e4], res);
    }
}

extern "C" void kernel_launch(void* const* d_in, const int* in_sizes, int n_in,
                              void* d_out, int out_size)
{
    const int*    X    = (const int*)d_in[0];
    const float4* emb  = (const float4*)d_in[1];
    const float4* c1   = (const float4*)d_in[2];
    const float4* c2   = (const float4*)d_in[3];
    const float4* c3   = (const float4*)d_in[4];
    const float4* c4   = (const float4*)d_in[5];
    float4*       out  = (float4*)d_out;

    dim3 grid(BATCH / ROWS_PER_CTA);   // 1024 CTAs per launch
    dim3 block(THREADS);
    for (int q = 0; q < NQ; ++q) {
        conv_cascade_q_kernel<<<grid, block>>>(X, emb, c1, c2, c3, c4, out,
                                               q * EQ4);
    }
}